// round 13
// baseline (speedup 1.0000x reference)
#include <cuda_runtime.h>

#define B_ 256
#define T_ 512
#define D_ 128
#define U_ 128
#define C_ 64
#define NSM 148

typedef unsigned long long ull;

__device__ __forceinline__ ull pk2(float x, float y) {
    ull r; asm("mov.b64 %0, {%1,%2};" : "=l"(r) : "f"(x), "f"(y)); return r;
}
__device__ __forceinline__ void upk2(ull v, float& x, float& y) {
    asm("mov.b64 {%0,%1}, %2;" : "=f"(x), "=f"(y) : "l"(v));
}
__device__ __forceinline__ ull ffma2(ull a, ull b, ull c) {
    ull d; asm("fma.rn.f32x2 %0, %1, %2, %3;" : "=l"(d) : "l"(a), "l"(b), "l"(c)); return d;
}
__device__ __forceinline__ float tanh_fast(float x) {
    float y; asm("tanh.approx.f32 %0, %1;" : "=f"(y) : "f"(x)); return y;
}

// smem layout (float offsets)
#define ST_ROW   136                   // ring row: 544B = 34x16
#define SM_W1P   0                     // float2[64][128] = 64KB
#define SM_WCP   16384                 // float2[64][64]  = 32KB
#define SM_HIST  24576                 // 32*136 floats   = 17KB
#define SM_HBUF  28928                 // 2*2048 floats   = 16KB
#define SM_XBUF  33024                 // 2*2048 floats   = 16KB
#define SM_TOTF  37120                 // 148480 bytes

// ---------------------------------------------------------------------------
// MEGA KERNEL: persistent, one chain per CTA at a time, grid = 148.
// tid 0..127  : recurrence (W2[:,j] in regs, per-step bar.sync 1,128),
//               h consumed from smem hbuf, y written to 32-deep ring.
// tid 128..255: head pipeline per 16-step block i:
//               (a) LDG X block i+2 -> xbuf, (b) H-GEMM block i+1
//               (X@W1+b1, tanh) -> hbuf, (c) out-GEMM block i-1 from ring.
// ---------------------------------------------------------------------------
__global__ void __launch_bounds__(256, 1)
k_mega(const float* __restrict__ X,  const float* __restrict__ W1,
       const float* __restrict__ b1, const float* __restrict__ W2,
       const float* __restrict__ b2, const float* __restrict__ Wc,
       const float* __restrict__ bc, float* __restrict__ out)
{
    extern __shared__ float sm[];
    float2* W1P  = (float2*)(sm + SM_W1P);
    float2* WcP  = (float2*)(sm + SM_WCP);
    float*  hist = sm + SM_HIST;
    float*  hbuf = sm + SM_HBUF;
    float*  xbuf = sm + SM_XBUF;

    const int tid = threadIdx.x;

    // one-time staging: W1 and Wc pair-interleaved over k
    for (int idx = tid; idx < 8192; idx += 256) {
        int kp = idx >> 7, c = idx & 127;
        W1P[idx] = make_float2(__ldg(W1 + (size_t)(2*kp)   * 128 + c),
                               __ldg(W1 + (size_t)(2*kp+1) * 128 + c));
    }
    for (int idx = tid; idx < 4096; idx += 256) {
        int kp = idx >> 6, c = idx & 63;
        WcP[idx] = make_float2(__ldg(Wc + (size_t)(2*kp)   * 64 + c),
                               __ldg(Wc + (size_t)(2*kp+1) * 64 + c));
    }

    if (tid < 128) {
        // ========================= RECURRENCE ROLE =========================
        const int j = tid;
        ull w[64];
        #pragma unroll
        for (int p = 0; p < 64; p++)
            w[p] = pk2(__ldg(W2 + (size_t)(2*p)*128 + j),
                       __ldg(W2 + (size_t)(2*p+1)*128 + j));
        const float b2v = __ldg(b2 + j);
        const int sidx = (j & 63) + (j >> 6) * 68;

        for (int chain = blockIdx.x; chain < B_; chain += NSM) {
            // prologue: help stage X block 0, reset y_{-1}
            {
                const float* Xc = X + (size_t)chain * (T_*128);
                #pragma unroll
                for (int kq = 0; kq < 2; kq++)
                    *(float4*)(xbuf + (tid + 256*kq)*4) =
                        *(const float4*)(Xc + (tid + 256*kq)*4);
            }
            hist[31 * ST_ROW + sidx] = 0.0f;
            __syncthreads();                        // P1
            __syncthreads();                        // P2 (head builds H blk0)

            #pragma unroll 1
            for (int i = 0; i <= 32; i++) {
                if (i < 32) {
                    const int t0 = i * 16;
                    const float* hb = hbuf + (i & 1) * 2048;
                    #pragma unroll 4
                    for (int u = 0; u < 16; u++) {
                        const int t = t0 + u;
                        float hv = hb[u * 128 + j];

                        const float* sb = hist + (((t + 31) & 31) * ST_ROW);
                        ull a0 = 0ULL, a1 = 0ULL, a2 = 0ULL, a3 = 0ULL;
                        #pragma unroll
                        for (int p = 0; p < 8; p++) {
                            ulonglong2 s0  = *(const ulonglong2*)(sb + 8*p);
                            ulonglong2 s1  = *(const ulonglong2*)(sb + 68 + 8*p);
                            a0 = ffma2(s0.x,  w[4*p+0],  a0);
                            a1 = ffma2(s0.y,  w[4*p+1],  a1);
                            a2 = ffma2(s1.x,  w[32+4*p], a2);
                            a3 = ffma2(s1.y,  w[33+4*p], a3);
                            ulonglong2 s0b = *(const ulonglong2*)(sb + 8*p + 4);
                            ulonglong2 s1b = *(const ulonglong2*)(sb + 68 + 8*p + 4);
                            a0 = ffma2(s0b.x, w[4*p+2],  a0);
                            a1 = ffma2(s0b.y, w[4*p+3],  a1);
                            a2 = ffma2(s1b.x, w[34+4*p], a2);
                            a3 = ffma2(s1b.y, w[35+4*p], a3);
                        }
                        float x0,y0,x1,y1,x2,y2,x3,y3;
                        upk2(a0,x0,y0); upk2(a1,x1,y1);
                        upk2(a2,x2,y2); upk2(a3,x3,y3);
                        float s = ((x0+y0)+(x1+y1)) + ((x2+y2)+(x3+y3)) + b2v;
                        float yv = hv + tanh_fast(s);

                        hist[(t & 31) * ST_ROW + sidx] = yv;
                        asm volatile("bar.sync 1, 128;" ::: "memory");
                    }
                }
                __syncthreads();                    // block boundary
            }
        }
    } else {
        // ============================ HEAD ROLE ============================
        const int h = tid - 128;                    // 0..127
        // H-GEMM mapping: rows rr..rr+3 (of 16), cols cc..cc+3 (of 128)
        const int rr = (h >> 5) * 4;
        const int cc = (h & 31) * 4;
        // out-GEMM mapping: rows r2,r2+1 (of 16), cols c4..c4+3 (of 64)
        const int r2 = (h >> 4) * 2;
        const int c4 = (h & 15) * 4;

        float bb1[4], bbc[4];
        #pragma unroll
        for (int c = 0; c < 4; c++) {
            bb1[c] = __ldg(b1 + cc + c);
            bbc[c] = __ldg(bc + c4 + c);
        }

        for (int chain = blockIdx.x; chain < B_; chain += NSM) {
            const float* Xc = X + (size_t)chain * (T_*128);

            // prologue: help stage X block 0
            #pragma unroll
            for (int kq = 0; kq < 2; kq++)
                *(float4*)(xbuf + (tid + 256*kq)*4) =
                    *(const float4*)(Xc + (tid + 256*kq)*4);
            __syncthreads();                        // P1

            // H-GEMM block 0 -> hbuf[0]; then stage X block 1 -> xbuf[1]
            {
                const float* xs = xbuf;             // block 0 in xbuf[0]
                ull acc[4][4];
                #pragma unroll
                for (int r = 0; r < 4; r++)
                    #pragma unroll
                    for (int c = 0; c < 4; c++) acc[r][c] = 0ULL;
                #pragma unroll 4
                for (int kp = 0; kp < 64; kp++) {
                    ulonglong2 w0 = *(const ulonglong2*)(W1P + kp*128 + cc);
                    ulonglong2 w1 = *(const ulonglong2*)(W1P + kp*128 + cc + 2);
                    #pragma unroll
                    for (int r = 0; r < 4; r++) {
                        ull xv = *(const ull*)(xs + (rr+r)*128 + 2*kp);
                        acc[r][0] = ffma2(xv, w0.x, acc[r][0]);
                        acc[r][1] = ffma2(xv, w0.y, acc[r][1]);
                        acc[r][2] = ffma2(xv, w1.x, acc[r][2]);
                        acc[r][3] = ffma2(xv, w1.y, acc[r][3]);
                    }
                }
                #pragma unroll
                for (int r = 0; r < 4; r++) {
                    float4 o; float x, y;
                    upk2(acc[r][0], x, y); o.x = tanh_fast(x + y + bb1[0]);
                    upk2(acc[r][1], x, y); o.y = tanh_fast(x + y + bb1[1]);
                    upk2(acc[r][2], x, y); o.z = tanh_fast(x + y + bb1[2]);
                    upk2(acc[r][3], x, y); o.w = tanh_fast(x + y + bb1[3]);
                    *(float4*)(hbuf + (rr+r)*128 + cc) = o;
                }
                // stage X block 1 -> xbuf[1]
                #pragma unroll
                for (int kq = 0; kq < 4; kq++)
                    *(float4*)(xbuf + 2048 + (h + 128*kq)*4) =
                        *(const float4*)(Xc + 2048 + (h + 128*kq)*4);
            }
            __syncthreads();                        // P2

            #pragma unroll 1
            for (int i = 0; i <= 32; i++) {
                // (a) LDG X block i+2 into regs (hide latency)
                float4 xr[4];
                const bool do_x = (i + 2 < 32);
                if (do_x) {
                    const float* src = Xc + (size_t)(i + 2) * 2048;
                    #pragma unroll
                    for (int kq = 0; kq < 4; kq++)
                        xr[kq] = *(const float4*)(src + (h + 128*kq)*4);
                }

                // (b) H-GEMM block i+1: xbuf[(i+1)&1] -> hbuf[(i+1)&1]
                if (i + 1 < 32) {
                    const float* xs = xbuf + ((i + 1) & 1) * 2048;
                    ull acc[4][4];
                    #pragma unroll
                    for (int r = 0; r < 4; r++)
                        #pragma unroll
                        for (int c = 0; c < 4; c++) acc[r][c] = 0ULL;
                    #pragma unroll 4
                    for (int kp = 0; kp < 64; kp++) {
                        ulonglong2 w0 = *(const ulonglong2*)(W1P + kp*128 + cc);
                        ulonglong2 w1 = *(const ulonglong2*)(W1P + kp*128 + cc + 2);
                        #pragma unroll
                        for (int r = 0; r < 4; r++) {
                            ull xv = *(const ull*)(xs + (rr+r)*128 + 2*kp);
                            acc[r][0] = ffma2(xv, w0.x, acc[r][0]);
                            acc[r][1] = ffma2(xv, w0.y, acc[r][1]);
                            acc[r][2] = ffma2(xv, w1.x, acc[r][2]);
                            acc[r][3] = ffma2(xv, w1.y, acc[r][3]);
                        }
                    }
                    float* hd = hbuf + ((i + 1) & 1) * 2048;
                    #pragma unroll
                    for (int r = 0; r < 4; r++) {
                        float4 o; float x, y;
                        upk2(acc[r][0], x, y); o.x = tanh_fast(x + y + bb1[0]);
                        upk2(acc[r][1], x, y); o.y = tanh_fast(x + y + bb1[1]);
                        upk2(acc[r][2], x, y); o.z = tanh_fast(x + y + bb1[2]);
                        upk2(acc[r][3], x, y); o.w = tanh_fast(x + y + bb1[3]);
                        *(float4*)(hd + (rr+r)*128 + cc) = o;
                    }
                }

                // store staged X block i+2 -> xbuf[i&1]
                if (do_x) {
                    float* dst = xbuf + (i & 1) * 2048;
                    #pragma unroll
                    for (int kq = 0; kq < 4; kq++)
                        *(float4*)(dst + (h + 128*kq)*4) = xr[kq];
                }

                // (c) out-GEMM block i-1 from the ring
                if (i >= 1) {
                    const int t0h = (i - 1) * 16;
                    const float* ya = hist + (((t0h + r2)     & 31) * ST_ROW);
                    const float* yb = hist + (((t0h + r2 + 1) & 31) * ST_ROW);
                    ull acc[2][4];
                    #pragma unroll
                    for (int r = 0; r < 2; r++)
                        #pragma unroll
                        for (int c = 0; c < 4; c++) acc[r][c] = 0ULL;
                    #pragma unroll 4
                    for (int kp = 0; kp < 64; kp++) {
                        const int off = (kp < 32) ? (2*kp) : (68 + 2*(kp-32));
                        ulonglong2 w0 = *(const ulonglong2*)(WcP + kp*64 + c4);
                        ulonglong2 w1 = *(const ulonglong2*)(WcP + kp*64 + c4 + 2);
                        ull y0 = *(const ull*)(ya + off);
                        ull y1 = *(const ull*)(yb + off);
                        acc[0][0] = ffma2(y0, w0.x, acc[0][0]);
                        acc[0][1] = ffma2(y0, w0.y, acc[0][1]);
                        acc[0][2] = ffma2(y0, w1.x, acc[0][2]);
                        acc[0][3] = ffma2(y0, w1.y, acc[0][3]);
                        acc[1][0] = ffma2(y1, w0.x, acc[1][0]);
                        acc[1][1] = ffma2(y1, w0.y, acc[1][1]);
                        acc[1][2] = ffma2(y1, w1.x, acc[1][2]);
                        acc[1][3] = ffma2(y1, w1.y, acc[1][3]);
                    }
                    #pragma unroll
                    for (int r = 0; r < 2; r++) {
                        float4 o; float x, y;
                        upk2(acc[r][0], x, y); o.x = x + y + bbc[0];
                        upk2(acc[r][1], x, y); o.y = x + y + bbc[1];
                        upk2(acc[r][2], x, y); o.z = x + y + bbc[2];
                        upk2(acc[r][3], x, y); o.w = x + y + bbc[3];
                        *(float4*)(out + ((size_t)chain * T_ + t0h + r2 + r) * 64 + c4) = o;
                    }
                }
                __syncthreads();                    // block boundary
            }
        }
    }
}

extern "C" void kernel_launch(void* const* d_in, const int* in_sizes, int n_in,
                              void* d_out, int out_size) {
    (void)in_sizes; (void)n_in; (void)out_size;
    const float* X  = (const float*)d_in[0];
    const float* W1 = (const float*)d_in[1];
    const float* b1 = (const float*)d_in[2];
    const float* W2 = (const float*)d_in[3];
    const float* b2 = (const float*)d_in[4];
    const float* Wc = (const float*)d_in[5];
    const float* bc = (const float*)d_in[6];
    float* out = (float*)d_out;

    cudaFuncSetAttribute(k_mega, cudaFuncAttributeMaxDynamicSharedMemorySize,
                         SM_TOTF * 4);
    k_mega<<<NSM, 256, SM_TOTF * 4>>>(X, W1, b1, W2, b2, Wc, bc, out);
}